// round 2
// baseline (speedup 1.0000x reference)
#include <cuda_runtime.h>

#define N_NODES 100000
#define N_EDGES 1600000
#define D_IN    64
#define D_H     128
#define D_M     256
#define D_OUT   40

// ---------------- scratch (device globals; no allocation in kernel_launch) ---
__device__ __align__(16) float g_agg1[(size_t)N_NODES * D_IN];   // 25.6 MB
__device__ __align__(16) float g_cnt [N_NODES];
__device__ __align__(16) float g_h1  [(size_t)N_NODES * D_H];    // 51.2 MB
__device__ __align__(16) float g_agg2[(size_t)N_NODES * D_H];    // 51.2 MB
__device__ __align__(16) float g_h2  [(size_t)N_NODES * D_H];    // 51.2 MB

__device__ __forceinline__ void red_add_v4(float* p, float4 v) {
    asm volatile("red.global.add.v4.f32 [%0], {%1,%2,%3,%4};"
                 :: "l"(p), "f"(v.x), "f"(v.y), "f"(v.z), "f"(v.w) : "memory");
}

__device__ __forceinline__ float sigmoidf_(float x) {
    return 1.0f / (1.0f + __expf(-x));
}

// ---------------- zero accumulators ------------------------------------------
__global__ void zero_kernel() {
    const unsigned T1 = N_NODES * D_IN / 4;   // agg1 float4 count
    const unsigned T2 = N_NODES * D_H / 4;    // agg2 float4 count
    const unsigned T3 = N_NODES / 4;          // cnt float4 count
    unsigned i = blockIdx.x * blockDim.x + threadIdx.x;
    unsigned stride = gridDim.x * blockDim.x;
    float4 z = make_float4(0.f, 0.f, 0.f, 0.f);
    for (unsigned j = i; j < T1; j += stride) ((float4*)g_agg1)[j] = z;
    for (unsigned j = i; j < T2; j += stride) ((float4*)g_agg2)[j] = z;
    for (unsigned j = i; j < T3; j += stride) ((float4*)g_cnt )[j] = z;
}

// ---------------- edge scatter, layer 1 (64 floats/edge, 16 thr/edge) --------
// edge_index is int32 (JAX x64 disabled downgrades jnp.int64 -> int32)
__global__ void scatter1_kernel(const float* __restrict__ feat,
                                const int* __restrict__ ei) {
    unsigned gid = blockIdx.x * blockDim.x + threadIdx.x;
    if (gid >= (unsigned)N_EDGES * 16u) return;
    unsigned e = gid >> 4;
    unsigned p = gid & 15u;
    int s = __ldg(&ei[e]);
    int d = __ldg(&ei[N_EDGES + e]);
    if ((unsigned)s >= (unsigned)N_NODES || (unsigned)d >= (unsigned)N_NODES) return;
    float4 v = __ldg((const float4*)(feat + (size_t)s * D_IN) + p);
    red_add_v4(g_agg1 + (size_t)d * D_IN + p * 4, v);
    if (p == 0) atomicAdd(&g_cnt[d], 1.0f);
}

// ---------------- edge scatter, layer 2 (128 floats/edge, 32 thr/edge) -------
__global__ void scatter2_kernel(const int* __restrict__ ei) {
    unsigned gid = blockIdx.x * blockDim.x + threadIdx.x;
    if (gid >= (unsigned)N_EDGES * 32u) return;
    unsigned e = gid >> 5;
    unsigned p = gid & 31u;
    int s = __ldg(&ei[e]);
    int d = __ldg(&ei[N_EDGES + e]);
    if ((unsigned)s >= (unsigned)N_NODES || (unsigned)d >= (unsigned)N_NODES) return;
    float4 v = __ldg((const float4*)(g_h1 + (size_t)s * D_H) + p);
    red_add_v4(g_agg2 + (size_t)d * D_H + p * 4, v);
}

// ---------------- layer-1 GEMM + sigmoid:  h1 = sig([x, agg1/cnt] @ W1 + b1) -
// block: 256 threads, 64 nodes.  smem: W1 [128][128] + in [64][132]
#define L1_SMEM ((128 * 128 + 64 * 132) * 4)
__global__ void __launch_bounds__(256, 2)
l1_gemm_kernel(const float* __restrict__ feat,
               const float* __restrict__ W1, const float* __restrict__ b1) {
    extern __shared__ float sm[];
    float* Ws  = sm;             // 16384 floats
    float* inS = sm + 128 * 128; // 64 * 132 floats
    int tid = threadIdx.x;
    int node0 = blockIdx.x * 64;

    for (int i = tid; i < 128 * 128 / 4; i += 256)
        ((float4*)Ws)[i] = __ldg((const float4*)W1 + i);

    for (int i = tid; i < 1024; i += 256) {           // self features
        int nd = i >> 4, q = i & 15;
        int gn = node0 + nd;
        float4 v = make_float4(0.f, 0.f, 0.f, 0.f);
        if (gn < N_NODES) v = __ldg((const float4*)(feat + (size_t)gn * D_IN) + q);
        *(float4*)&inS[nd * 132 + q * 4] = v;
    }
    for (int i = tid; i < 1024; i += 256) {           // neighbor mean
        int nd = i >> 4, q = i & 15;
        int gn = node0 + nd;
        float4 v = make_float4(0.f, 0.f, 0.f, 0.f);
        if (gn < N_NODES) {
            v = __ldg((const float4*)(g_agg1 + (size_t)gn * D_IN) + q);
            float sc = 1.0f / fmaxf(__ldg(&g_cnt[gn]), 1.0f);
            v.x *= sc; v.y *= sc; v.z *= sc; v.w *= sc;
        }
        *(float4*)&inS[nd * 132 + 64 + q * 4] = v;
    }
    __syncthreads();

    int cg = tid & 15;   // 8 cols per group
    int ng = tid >> 4;   // 4 nodes per group
    const float* ip = &inS[ng * 4 * 132];
    int cg8 = cg * 8;

    float acc[4][8];
#pragma unroll
    for (int i = 0; i < 4; i++)
#pragma unroll
        for (int j = 0; j < 8; j++) acc[i][j] = 0.f;

#pragma unroll 4
    for (int k = 0; k < 128; ++k) {
        float a0 = ip[k], a1 = ip[132 + k], a2 = ip[264 + k], a3 = ip[396 + k];
        float4 bA = *(const float4*)&Ws[k * 128 + cg8];
        float4 bB = *(const float4*)&Ws[k * 128 + cg8 + 4];
        float a[4] = {a0, a1, a2, a3};
#pragma unroll
        for (int i = 0; i < 4; i++) {
            acc[i][0] += a[i] * bA.x; acc[i][1] += a[i] * bA.y;
            acc[i][2] += a[i] * bA.z; acc[i][3] += a[i] * bA.w;
            acc[i][4] += a[i] * bB.x; acc[i][5] += a[i] * bB.y;
            acc[i][6] += a[i] * bB.z; acc[i][7] += a[i] * bB.w;
        }
    }

    float bb[8];
#pragma unroll
    for (int j = 0; j < 8; j++) bb[j] = __ldg(&b1[cg8 + j]);
#pragma unroll
    for (int i = 0; i < 4; i++) {
        int gn = node0 + ng * 4 + i;
        if (gn < N_NODES) {
            float4 o0, o1;
            o0.x = sigmoidf_(acc[i][0] + bb[0]); o0.y = sigmoidf_(acc[i][1] + bb[1]);
            o0.z = sigmoidf_(acc[i][2] + bb[2]); o0.w = sigmoidf_(acc[i][3] + bb[3]);
            o1.x = sigmoidf_(acc[i][4] + bb[4]); o1.y = sigmoidf_(acc[i][5] + bb[5]);
            o1.z = sigmoidf_(acc[i][6] + bb[6]); o1.w = sigmoidf_(acc[i][7] + bb[7]);
            float* dst = g_h1 + (size_t)gn * D_H + cg8;
            *(float4*)dst = o0;
            *(float4*)(dst + 4) = o1;
        }
    }
}

// ---------------- layer-2 GEMM + sigmoid:  h2 = sig([h1, agg2/cnt] @ W2 + b2)
// block: 256 threads, 64 nodes.  smem: W2 [256][128] + in [64][260]
#define L2_SMEM ((256 * 128 + 64 * 260) * 4)
__global__ void __launch_bounds__(256, 1)
l2_gemm_kernel(const float* __restrict__ W2, const float* __restrict__ b2) {
    extern __shared__ float sm[];
    float* Ws  = sm;             // 32768 floats
    float* inS = sm + 256 * 128; // 64 * 260 floats
    int tid = threadIdx.x;
    int node0 = blockIdx.x * 64;

    for (int i = tid; i < 256 * 128 / 4; i += 256)
        ((float4*)Ws)[i] = __ldg((const float4*)W2 + i);

    for (int i = tid; i < 2048; i += 256) {           // self (h1)
        int nd = i >> 5, q = i & 31;
        int gn = node0 + nd;
        float4 v = make_float4(0.f, 0.f, 0.f, 0.f);
        if (gn < N_NODES) v = __ldg((const float4*)(g_h1 + (size_t)gn * D_H) + q);
        *(float4*)&inS[nd * 260 + q * 4] = v;
    }
    for (int i = tid; i < 2048; i += 256) {           // neighbor mean
        int nd = i >> 5, q = i & 31;
        int gn = node0 + nd;
        float4 v = make_float4(0.f, 0.f, 0.f, 0.f);
        if (gn < N_NODES) {
            v = __ldg((const float4*)(g_agg2 + (size_t)gn * D_H) + q);
            float sc = 1.0f / fmaxf(__ldg(&g_cnt[gn]), 1.0f);
            v.x *= sc; v.y *= sc; v.z *= sc; v.w *= sc;
        }
        *(float4*)&inS[nd * 260 + 128 + q * 4] = v;
    }
    __syncthreads();

    int cg = tid & 15;
    int ng = tid >> 4;
    const float* ip = &inS[ng * 4 * 260];
    int cg8 = cg * 8;

    float acc[4][8];
#pragma unroll
    for (int i = 0; i < 4; i++)
#pragma unroll
        for (int j = 0; j < 8; j++) acc[i][j] = 0.f;

#pragma unroll 4
    for (int k = 0; k < 256; ++k) {
        float a0 = ip[k], a1 = ip[260 + k], a2 = ip[520 + k], a3 = ip[780 + k];
        float4 bA = *(const float4*)&Ws[k * 128 + cg8];
        float4 bB = *(const float4*)&Ws[k * 128 + cg8 + 4];
        float a[4] = {a0, a1, a2, a3};
#pragma unroll
        for (int i = 0; i < 4; i++) {
            acc[i][0] += a[i] * bA.x; acc[i][1] += a[i] * bA.y;
            acc[i][2] += a[i] * bA.z; acc[i][3] += a[i] * bA.w;
            acc[i][4] += a[i] * bB.x; acc[i][5] += a[i] * bB.y;
            acc[i][6] += a[i] * bB.z; acc[i][7] += a[i] * bB.w;
        }
    }

    float bb[8];
#pragma unroll
    for (int j = 0; j < 8; j++) bb[j] = __ldg(&b2[cg8 + j]);
#pragma unroll
    for (int i = 0; i < 4; i++) {
        int gn = node0 + ng * 4 + i;
        if (gn < N_NODES) {
            float4 o0, o1;
            o0.x = sigmoidf_(acc[i][0] + bb[0]); o0.y = sigmoidf_(acc[i][1] + bb[1]);
            o0.z = sigmoidf_(acc[i][2] + bb[2]); o0.w = sigmoidf_(acc[i][3] + bb[3]);
            o1.x = sigmoidf_(acc[i][4] + bb[4]); o1.y = sigmoidf_(acc[i][5] + bb[5]);
            o1.z = sigmoidf_(acc[i][6] + bb[6]); o1.w = sigmoidf_(acc[i][7] + bb[7]);
            float* dst = g_h2 + (size_t)gn * D_H + cg8;
            *(float4*)dst = o0;
            *(float4*)(dst + 4) = o1;
        }
    }
}

// ---------------- fused MLP:  out = relu(h2 @ Wm1 + bm1) @ Wm2 + bm2 ---------
// block: 256 threads, 32 nodes. smem: Wm1 [128][256] + Wm2 [256][40]
//                                   + in [32][132] + h3 [32][259]
#define MLP_SMEM ((128 * 256 + 256 * 40 + 32 * 132 + 32 * 259) * 4)
__global__ void __launch_bounds__(256, 1)
mlp_kernel(const float* __restrict__ Wm1, const float* __restrict__ bm1,
           const float* __restrict__ Wm2, const float* __restrict__ bm2,
           float* __restrict__ out) {
    extern __shared__ float sm[];
    float* W1s = sm;                       // 32768
    float* W2s = W1s + 128 * 256;          // 10240
    float* inS = W2s + 256 * 40;           // 32*132 = 4224
    float* h3S = inS + 32 * 132;           // 32*259 = 8288
    int tid = threadIdx.x;
    int node0 = blockIdx.x * 32;

    for (int i = tid; i < 128 * 256 / 4; i += 256)
        ((float4*)W1s)[i] = __ldg((const float4*)Wm1 + i);
    for (int i = tid; i < 256 * 40 / 4; i += 256)
        ((float4*)W2s)[i] = __ldg((const float4*)Wm2 + i);
    for (int i = tid; i < 1024; i += 256) {
        int nd = i >> 5, q = i & 31;
        int gn = node0 + nd;
        float4 v = make_float4(0.f, 0.f, 0.f, 0.f);
        if (gn < N_NODES) v = __ldg((const float4*)(g_h2 + (size_t)gn * D_H) + q);
        *(float4*)&inS[nd * 132 + q * 4] = v;
    }
    __syncthreads();

    // GEMM1: [32,128] @ [128,256] -> relu -> h3S
    {
        int cg = tid & 31;   // 8 cols per group  (32*8=256)
        int ng = tid >> 5;   // 4 nodes per group (8*4=32)
        const float* ip = &inS[ng * 4 * 132];
        int cg8 = cg * 8;
        float acc[4][8];
#pragma unroll
        for (int i = 0; i < 4; i++)
#pragma unroll
            for (int j = 0; j < 8; j++) acc[i][j] = 0.f;

#pragma unroll 4
        for (int k = 0; k < 128; ++k) {
            float a0 = ip[k], a1 = ip[132 + k], a2 = ip[264 + k], a3 = ip[396 + k];
            float4 bA = *(const float4*)&W1s[k * 256 + cg8];
            float4 bB = *(const float4*)&W1s[k * 256 + cg8 + 4];
            float a[4] = {a0, a1, a2, a3};
#pragma unroll
            for (int i = 0; i < 4; i++) {
                acc[i][0] += a[i] * bA.x; acc[i][1] += a[i] * bA.y;
                acc[i][2] += a[i] * bA.z; acc[i][3] += a[i] * bA.w;
                acc[i][4] += a[i] * bB.x; acc[i][5] += a[i] * bB.y;
                acc[i][6] += a[i] * bB.z; acc[i][7] += a[i] * bB.w;
            }
        }
        float bb[8];
#pragma unroll
        for (int j = 0; j < 8; j++) bb[j] = __ldg(&bm1[cg8 + j]);
#pragma unroll
        for (int i = 0; i < 4; i++)
#pragma unroll
            for (int j = 0; j < 8; j++)
                h3S[(ng * 4 + i) * 259 + cg8 + j] = fmaxf(acc[i][j] + bb[j], 0.f);
    }
    __syncthreads();

    // GEMM2: [32,256] @ [256,40] -> out
    {
        int nd  = tid & 31;  // node within tile
        int cg2 = tid >> 5;  // 5 cols per group (8*5=40)
        const float* hp = &h3S[nd * 259];
        int c0 = cg2 * 5;
        float o[5] = {0.f, 0.f, 0.f, 0.f, 0.f};
#pragma unroll 4
        for (int k = 0; k < 256; ++k) {
            float a = hp[k];
            const float* wp = &W2s[k * 40 + c0];
            o[0] += a * wp[0]; o[1] += a * wp[1]; o[2] += a * wp[2];
            o[3] += a * wp[3]; o[4] += a * wp[4];
        }
        int gn = node0 + nd;
        if (gn < N_NODES) {
            float* op = out + (size_t)gn * D_OUT + c0;
#pragma unroll
            for (int j = 0; j < 5; j++) op[j] = o[j] + __ldg(&bm2[c0 + j]);
        }
    }
}

// ---------------- launch -----------------------------------------------------
extern "C" void kernel_launch(void* const* d_in, const int* in_sizes, int n_in,
                              void* d_out, int out_size) {
    const float* feat = (const float*)d_in[0];
    const int*   ei   = (const int*)d_in[1];     // int32! (JAX x64 disabled)
    const float* W1   = (const float*)d_in[2];
    const float* b1   = (const float*)d_in[3];
    const float* W2   = (const float*)d_in[4];
    const float* b2   = (const float*)d_in[5];
    const float* Wm1  = (const float*)d_in[6];
    const float* bm1  = (const float*)d_in[7];
    const float* Wm2  = (const float*)d_in[8];
    const float* bm2  = (const float*)d_in[9];
    float* out = (float*)d_out;

    cudaFuncSetAttribute(l1_gemm_kernel, cudaFuncAttributeMaxDynamicSharedMemorySize, L1_SMEM);
    cudaFuncSetAttribute(l2_gemm_kernel, cudaFuncAttributeMaxDynamicSharedMemorySize, L2_SMEM);
    cudaFuncSetAttribute(mlp_kernel,     cudaFuncAttributeMaxDynamicSharedMemorySize, MLP_SMEM);

    zero_kernel<<<2048, 256>>>();

    {   // layer-1 scatter: 16 threads/edge
        unsigned total = (unsigned)N_EDGES * 16u;
        scatter1_kernel<<<(total + 255) / 256, 256>>>(feat, ei);
    }
    l1_gemm_kernel<<<(N_NODES + 63) / 64, 256, L1_SMEM>>>(feat, W1, b1);

    {   // layer-2 scatter: 32 threads/edge
        unsigned total = (unsigned)N_EDGES * 32u;
        scatter2_kernel<<<(total + 255) / 256, 256>>>(ei);
    }
    l2_gemm_kernel<<<(N_NODES + 63) / 64, 256, L2_SMEM>>>(W2, b2);

    mlp_kernel<<<(N_NODES + 31) / 32, 256, MLP_SMEM>>>(Wm1, bm1, Wm2, bm2, out);
}

// round 3
// speedup vs baseline: 1.2586x; 1.2586x over previous
#include <cuda_runtime.h>
#include <cuda_bf16.h>

#define N_NODES 100000
#define N_EDGES 1600000
#define D_IN    64
#define D_H     128
#define D_M     256
#define D_OUT   40

// ---------------- device-global scratch --------------------------------------
__device__ __align__(16) float g_agg1[(size_t)N_NODES * D_IN];   // 25.6 MB
__device__ __align__(16) float g_agg2[(size_t)N_NODES * D_H];    // 51.2 MB
__device__ __align__(16) float g_cnt [N_NODES];
__device__ __align__(16) __nv_bfloat16 g_h1hi[(size_t)N_NODES * D_H];
__device__ __align__(16) __nv_bfloat16 g_h1lo[(size_t)N_NODES * D_H];
__device__ __align__(16) __nv_bfloat16 g_h2hi[(size_t)N_NODES * D_H];
__device__ __align__(16) __nv_bfloat16 g_h2lo[(size_t)N_NODES * D_H];
__device__ __align__(16) __nv_bfloat16 g_h3hi[(size_t)N_NODES * D_M];
__device__ __align__(16) __nv_bfloat16 g_h3lo[(size_t)N_NODES * D_M];

// ---------------- helpers ----------------------------------------------------
__device__ __forceinline__ void red_add_v4(float* p, float4 v) {
    asm volatile("red.global.add.v4.f32 [%0], {%1,%2,%3,%4};"
                 :: "l"(p), "f"(v.x), "f"(v.y), "f"(v.z), "f"(v.w) : "memory");
}
__device__ __forceinline__ float sigmoidf_(float x) {
    return 1.0f / (1.0f + __expf(-x));
}
__device__ __forceinline__ void split2(float x, __nv_bfloat16& hi, __nv_bfloat16& lo) {
    hi = __float2bfloat16(x);
    lo = __float2bfloat16(x - __bfloat162float(hi));
}
__device__ __forceinline__ unsigned pack_bf2(__nv_bfloat16 a, __nv_bfloat16 b) {
    return (unsigned)__bfloat16_as_ushort(a) | ((unsigned)__bfloat16_as_ushort(b) << 16);
}
__device__ __forceinline__ float2 bf2f2(unsigned u) {
    __nv_bfloat162 b = *(__nv_bfloat162*)&u;
    return __bfloat1622float2(b);
}

__device__ __forceinline__ void mma_bf16(float c[4], const unsigned a[4],
                                         unsigned b0, unsigned b1) {
    asm volatile("mma.sync.aligned.m16n8k16.row.col.f32.bf16.bf16.f32 "
                 "{%0,%1,%2,%3}, {%4,%5,%6,%7}, {%8,%9}, {%0,%1,%2,%3};"
                 : "+f"(c[0]), "+f"(c[1]), "+f"(c[2]), "+f"(c[3])
                 : "r"(a[0]), "r"(a[1]), "r"(a[2]), "r"(a[3]), "r"(b0), "r"(b1));
}

// one k16 step of a 32x(NF*8) warp tile with hi/lo error compensation
template<int NF>
__device__ __forceinline__ void mma_step(
    float (&acc)[2][NF][4],
    const __nv_bfloat16* __restrict__ Ahi, const __nv_bfloat16* __restrict__ Alo, int KPa,
    const __nv_bfloat16* __restrict__ Whi, const __nv_bfloat16* __restrict__ Wlo, int KPw,
    int m0, int n0, int kbA, int kbW, int g, int t)
{
    unsigned ah[2][4], al[2][4];
#pragma unroll
    for (int mf = 0; mf < 2; mf++) {
        int r = m0 + mf * 16 + g;
        ah[mf][0] = *(const unsigned*)&Ahi[(r    ) * KPa + kbA     + t * 2];
        ah[mf][1] = *(const unsigned*)&Ahi[(r + 8) * KPa + kbA     + t * 2];
        ah[mf][2] = *(const unsigned*)&Ahi[(r    ) * KPa + kbA + 8 + t * 2];
        ah[mf][3] = *(const unsigned*)&Ahi[(r + 8) * KPa + kbA + 8 + t * 2];
        al[mf][0] = *(const unsigned*)&Alo[(r    ) * KPa + kbA     + t * 2];
        al[mf][1] = *(const unsigned*)&Alo[(r + 8) * KPa + kbA     + t * 2];
        al[mf][2] = *(const unsigned*)&Alo[(r    ) * KPa + kbA + 8 + t * 2];
        al[mf][3] = *(const unsigned*)&Alo[(r + 8) * KPa + kbA + 8 + t * 2];
    }
#pragma unroll
    for (int nf = 0; nf < NF; nf++) {
        int n = n0 + nf * 8 + g;
        unsigned bh0 = *(const unsigned*)&Whi[n * KPw + kbW     + t * 2];
        unsigned bh1 = *(const unsigned*)&Whi[n * KPw + kbW + 8 + t * 2];
        unsigned bl0 = *(const unsigned*)&Wlo[n * KPw + kbW     + t * 2];
        unsigned bl1 = *(const unsigned*)&Wlo[n * KPw + kbW + 8 + t * 2];
#pragma unroll
        for (int mf = 0; mf < 2; mf++) {
            mma_bf16(acc[mf][nf], ah[mf], bh0, bh1);
            mma_bf16(acc[mf][nf], ah[mf], bl0, bl1);
            mma_bf16(acc[mf][nf], al[mf], bh0, bh1);
        }
    }
}

// ---------------- zero accumulators ------------------------------------------
__global__ void zero_kernel() {
    const unsigned T1 = N_NODES * D_IN / 4;
    const unsigned T2 = N_NODES * D_H / 4;
    const unsigned T3 = N_NODES / 4;
    unsigned i = blockIdx.x * blockDim.x + threadIdx.x;
    unsigned stride = gridDim.x * blockDim.x;
    float4 z = make_float4(0.f, 0.f, 0.f, 0.f);
    for (unsigned j = i; j < T1; j += stride) ((float4*)g_agg1)[j] = z;
    for (unsigned j = i; j < T2; j += stride) ((float4*)g_agg2)[j] = z;
    for (unsigned j = i; j < T3; j += stride) ((float4*)g_cnt )[j] = z;
}

// ---------------- scatters ---------------------------------------------------
__global__ void scatter1_kernel(const float* __restrict__ feat,
                                const int* __restrict__ ei) {
    unsigned gid = blockIdx.x * blockDim.x + threadIdx.x;
    if (gid >= (unsigned)N_EDGES * 16u) return;
    unsigned e = gid >> 4, p = gid & 15u;
    int s = __ldg(&ei[e]);
    int d = __ldg(&ei[N_EDGES + e]);
    if ((unsigned)s >= (unsigned)N_NODES || (unsigned)d >= (unsigned)N_NODES) return;
    float4 v = __ldg((const float4*)(feat + (size_t)s * D_IN) + p);
    red_add_v4(g_agg1 + (size_t)d * D_IN + p * 4, v);
    if (p == 0) atomicAdd(&g_cnt[d], 1.0f);
}

__global__ void scatter2_kernel(const int* __restrict__ ei) {
    unsigned gid = blockIdx.x * blockDim.x + threadIdx.x;
    if (gid >= (unsigned)N_EDGES * 32u) return;
    unsigned e = gid >> 5, p = gid & 31u;
    int s = __ldg(&ei[e]);
    int d = __ldg(&ei[N_EDGES + e]);
    if ((unsigned)s >= (unsigned)N_NODES || (unsigned)d >= (unsigned)N_NODES) return;
    size_t off = (size_t)s * D_H + p * 4;
    uint2 vh = *(const uint2*)(g_h1hi + off);
    uint2 vl = *(const uint2*)(g_h1lo + off);
    float2 a = bf2f2(vh.x), b = bf2f2(vh.y), c = bf2f2(vl.x), dd = bf2f2(vl.y);
    float4 v = make_float4(a.x + c.x, a.y + c.y, b.x + dd.x, b.y + dd.y);
    red_add_v4(g_agg2 + (size_t)d * D_H + p * 4, v);
}

// ============================================================================
// Layer-1: h1 = sigmoid([feat | agg1/cnt] @ W1 + b1)   (M=128/blk, N=128, K=128)
// ============================================================================
#define KP128 136
#define L1_SMEM ((4 * 128 * KP128) * 2 + 128 * 4)
__global__ void __launch_bounds__(256, 1)
l1_mma_kernel(const float* __restrict__ feat,
              const float* __restrict__ W1, const float* __restrict__ b1) {
    extern __shared__ unsigned char smraw[];
    __nv_bfloat16* Ahi = (__nv_bfloat16*)smraw;
    __nv_bfloat16* Alo = Ahi + 128 * KP128;
    __nv_bfloat16* Whi = Alo + 128 * KP128;
    __nv_bfloat16* Wlo = Whi + 128 * KP128;
    float* rcpS = (float*)(Wlo + 128 * KP128);
    int tid = threadIdx.x;
    int node0 = blockIdx.x * 128;

    for (int r = tid; r < 128; r += 256) {
        int gn = node0 + r;
        rcpS[r] = (gn < N_NODES) ? 1.0f / fmaxf(__ldg(&g_cnt[gn]), 1.0f) : 0.f;
    }
    __syncthreads();

    for (int i = tid; i < 128 * 128; i += 256) {   // W1: [128][128] -> Wt[n][k]
        int k = i >> 7, n = i & 127;
        __nv_bfloat16 h, l; split2(__ldg(&W1[i]), h, l);
        Whi[n * KP128 + k] = h; Wlo[n * KP128 + k] = l;
    }
    for (int i = tid; i < 128 * 128; i += 256) {   // A = [feat | agg1/cnt]
        int r = i >> 7, c = i & 127;
        int gn = node0 + r;
        float x = 0.f;
        if (gn < N_NODES)
            x = (c < 64) ? __ldg(&feat[(size_t)gn * 64 + c])
                         : g_agg1[(size_t)gn * 64 + (c - 64)] * rcpS[r];
        __nv_bfloat16 h, l; split2(x, h, l);
        Ahi[r * KP128 + c] = h; Alo[r * KP128 + c] = l;
    }
    __syncthreads();

    int w = tid >> 5, lane = tid & 31, g = lane >> 2, t = lane & 3;
    int m0 = (w & 3) * 32, n0 = (w >> 2) * 64;
    float acc[2][8][4];
#pragma unroll
    for (int a = 0; a < 2; a++)
#pragma unroll
        for (int b = 0; b < 8; b++)
#pragma unroll
            for (int c = 0; c < 4; c++) acc[a][b][c] = 0.f;

#pragma unroll
    for (int ks = 0; ks < 8; ks++)
        mma_step<8>(acc, Ahi, Alo, KP128, Whi, Wlo, KP128,
                    m0, n0, ks * 16, ks * 16, g, t);

#pragma unroll
    for (int mf = 0; mf < 2; mf++) {
        int r0 = node0 + m0 + mf * 16 + g;
#pragma unroll
        for (int nf = 0; nf < 8; nf++) {
            int col = n0 + nf * 8 + t * 2;
            float2 bv = *(const float2*)&b1[col];
            if (r0 < N_NODES) {
                float v0 = sigmoidf_(acc[mf][nf][0] + bv.x);
                float v1 = sigmoidf_(acc[mf][nf][1] + bv.y);
                __nv_bfloat16 h0, l0, h1, l1; split2(v0, h0, l0); split2(v1, h1, l1);
                size_t idx = (size_t)r0 * D_H + col;
                *(unsigned*)&g_h1hi[idx] = pack_bf2(h0, h1);
                *(unsigned*)&g_h1lo[idx] = pack_bf2(l0, l1);
            }
            if (r0 + 8 < N_NODES) {
                float v0 = sigmoidf_(acc[mf][nf][2] + bv.x);
                float v1 = sigmoidf_(acc[mf][nf][3] + bv.y);
                __nv_bfloat16 h0, l0, h1, l1; split2(v0, h0, l0); split2(v1, h1, l1);
                size_t idx = (size_t)(r0 + 8) * D_H + col;
                *(unsigned*)&g_h1hi[idx] = pack_bf2(h0, h1);
                *(unsigned*)&g_h1lo[idx] = pack_bf2(l0, l1);
            }
        }
    }
}

// ============================================================================
// Layer-2: h2 = sigmoid([h1 | agg2/cnt] @ W2 + b2)   (M=128/blk, N=128, K=256)
// ============================================================================
#define KP256 264
#define L2_SMEM ((2 * 128 * KP128 + 2 * 128 * KP256) * 2 + 128 * 4)
__global__ void __launch_bounds__(256, 1)
l2_mma_kernel(const float* __restrict__ W2, const float* __restrict__ b2) {
    extern __shared__ unsigned char smraw[];
    __nv_bfloat16* Ahi = (__nv_bfloat16*)smraw;            // [128][KP128] (k-chunk)
    __nv_bfloat16* Alo = Ahi + 128 * KP128;
    __nv_bfloat16* Whi = Alo + 128 * KP128;                // [128][KP256] full K
    __nv_bfloat16* Wlo = Whi + 128 * KP256;
    float* rcpS = (float*)(Wlo + 128 * KP256);
    int tid = threadIdx.x;
    int node0 = blockIdx.x * 128;

    for (int r = tid; r < 128; r += 256) {
        int gn = node0 + r;
        rcpS[r] = (gn < N_NODES) ? 1.0f / fmaxf(__ldg(&g_cnt[gn]), 1.0f) : 0.f;
    }
    for (int i = tid; i < 256 * 128; i += 256) {    // W2: [256][128] -> Wt[n][k]
        int k = i >> 7, n = i & 127;
        __nv_bfloat16 h, l; split2(__ldg(&W2[i]), h, l);
        Whi[n * KP256 + k] = h; Wlo[n * KP256 + k] = l;
    }
    for (int i = tid; i < 128 * 64; i += 256) {     // A chunk0 = copy of h1 hi/lo
        int r = i >> 6, c2 = (i & 63) * 2;
        int gn = node0 + r;
        unsigned vh = 0, vl = 0;
        if (gn < N_NODES) {
            vh = *(const unsigned*)&g_h1hi[(size_t)gn * D_H + c2];
            vl = *(const unsigned*)&g_h1lo[(size_t)gn * D_H + c2];
        }
        *(unsigned*)&Ahi[r * KP128 + c2] = vh;
        *(unsigned*)&Alo[r * KP128 + c2] = vl;
    }
    __syncthreads();

    int w = tid >> 5, lane = tid & 31, g = lane >> 2, t = lane & 3;
    int m0 = (w & 3) * 32, n0 = (w >> 2) * 64;
    float acc[2][8][4];
#pragma unroll
    for (int a = 0; a < 2; a++)
#pragma unroll
        for (int b = 0; b < 8; b++)
#pragma unroll
            for (int c = 0; c < 4; c++) acc[a][b][c] = 0.f;

#pragma unroll
    for (int ks = 0; ks < 8; ks++)
        mma_step<8>(acc, Ahi, Alo, KP128, Whi, Wlo, KP256,
                    m0, n0, ks * 16, ks * 16, g, t);
    __syncthreads();

    for (int i = tid; i < 128 * 128; i += 256) {    // A chunk1 = agg2/cnt
        int r = i >> 7, c = i & 127;
        int gn = node0 + r;
        float x = (gn < N_NODES) ? g_agg2[(size_t)gn * D_H + c] * rcpS[r] : 0.f;
        __nv_bfloat16 h, l; split2(x, h, l);
        Ahi[r * KP128 + c] = h; Alo[r * KP128 + c] = l;
    }
    __syncthreads();

#pragma unroll
    for (int ks = 0; ks < 8; ks++)
        mma_step<8>(acc, Ahi, Alo, KP128, Whi, Wlo, KP256,
                    m0, n0, ks * 16, 128 + ks * 16, g, t);

#pragma unroll
    for (int mf = 0; mf < 2; mf++) {
        int r0 = node0 + m0 + mf * 16 + g;
#pragma unroll
        for (int nf = 0; nf < 8; nf++) {
            int col = n0 + nf * 8 + t * 2;
            float2 bv = *(const float2*)&b2[col];
            if (r0 < N_NODES) {
                float v0 = sigmoidf_(acc[mf][nf][0] + bv.x);
                float v1 = sigmoidf_(acc[mf][nf][1] + bv.y);
                __nv_bfloat16 h0, l0, h1, l1; split2(v0, h0, l0); split2(v1, h1, l1);
                size_t idx = (size_t)r0 * D_H + col;
                *(unsigned*)&g_h2hi[idx] = pack_bf2(h0, h1);
                *(unsigned*)&g_h2lo[idx] = pack_bf2(l0, l1);
            }
            if (r0 + 8 < N_NODES) {
                float v0 = sigmoidf_(acc[mf][nf][2] + bv.x);
                float v1 = sigmoidf_(acc[mf][nf][3] + bv.y);
                __nv_bfloat16 h0, l0, h1, l1; split2(v0, h0, l0); split2(v1, h1, l1);
                size_t idx = (size_t)(r0 + 8) * D_H + col;
                *(unsigned*)&g_h2hi[idx] = pack_bf2(h0, h1);
                *(unsigned*)&g_h2lo[idx] = pack_bf2(l0, l1);
            }
        }
    }
}

// ============================================================================
// MLP-1: h3 = relu(h2 @ Wm1 + bm1)   (M=128/blk, N=256 in two 128-halves, K=128)
// ============================================================================
#define M1_SMEM ((4 * 128 * KP128) * 2)
__global__ void __launch_bounds__(256, 1)
m1_mma_kernel(const float* __restrict__ Wm1, const float* __restrict__ bm1) {
    extern __shared__ unsigned char smraw[];
    __nv_bfloat16* Ahi = (__nv_bfloat16*)smraw;
    __nv_bfloat16* Alo = Ahi + 128 * KP128;
    __nv_bfloat16* Whi = Alo + 128 * KP128;   // [128 n][KP128] per n-half
    __nv_bfloat16* Wlo = Whi + 128 * KP128;
    int tid = threadIdx.x;
    int node0 = blockIdx.x * 128;

    for (int i = tid; i < 128 * 64; i += 256) {     // A = copy of h2 hi/lo
        int r = i >> 6, c2 = (i & 63) * 2;
        int gn = node0 + r;
        unsigned vh = 0, vl = 0;
        if (gn < N_NODES) {
            vh = *(const unsigned*)&g_h2hi[(size_t)gn * D_H + c2];
            vl = *(const unsigned*)&g_h2lo[(size_t)gn * D_H + c2];
        }
        *(unsigned*)&Ahi[r * KP128 + c2] = vh;
        *(unsigned*)&Alo[r * KP128 + c2] = vl;
    }

    int w = tid >> 5, lane = tid & 31, g = lane >> 2, t = lane & 3;
    int m0 = (w & 3) * 32, n0 = (w >> 2) * 64;

    for (int nb = 0; nb < 2; nb++) {
        if (nb) __syncthreads();
        for (int i = tid; i < 128 * 128; i += 256) {  // W half: cols nb*128..+128
            int k = i >> 7, n = i & 127;
            __nv_bfloat16 h, l; split2(__ldg(&Wm1[k * 256 + nb * 128 + n]), h, l);
            Whi[n * KP128 + k] = h; Wlo[n * KP128 + k] = l;
        }
        __syncthreads();

        float acc[2][8][4];
#pragma unroll
        for (int a = 0; a < 2; a++)
#pragma unroll
            for (int b = 0; b < 8; b++)
#pragma unroll
                for (int c = 0; c < 4; c++) acc[a][b][c] = 0.f;

#pragma unroll
        for (int ks = 0; ks < 8; ks++)
            mma_step<8>(acc, Ahi, Alo, KP128, Whi, Wlo, KP128,
                        m0, n0, ks * 16, ks * 16, g, t);

#pragma unroll
        for (int mf = 0; mf < 2; mf++) {
            int r0 = node0 + m0 + mf * 16 + g;
#pragma unroll
            for (int nf = 0; nf < 8; nf++) {
                int col = nb * 128 + n0 + nf * 8 + t * 2;
                float2 bv = *(const float2*)&bm1[col];
                if (r0 < N_NODES) {
                    float v0 = fmaxf(acc[mf][nf][0] + bv.x, 0.f);
                    float v1 = fmaxf(acc[mf][nf][1] + bv.y, 0.f);
                    __nv_bfloat16 h0, l0, h1, l1; split2(v0, h0, l0); split2(v1, h1, l1);
                    size_t idx = (size_t)r0 * D_M + col;
                    *(unsigned*)&g_h3hi[idx] = pack_bf2(h0, h1);
                    *(unsigned*)&g_h3lo[idx] = pack_bf2(l0, l1);
                }
                if (r0 + 8 < N_NODES) {
                    float v0 = fmaxf(acc[mf][nf][2] + bv.x, 0.f);
                    float v1 = fmaxf(acc[mf][nf][3] + bv.y, 0.f);
                    __nv_bfloat16 h0, l0, h1, l1; split2(v0, h0, l0); split2(v1, h1, l1);
                    size_t idx = (size_t)(r0 + 8) * D_M + col;
                    *(unsigned*)&g_h3hi[idx] = pack_bf2(h0, h1);
                    *(unsigned*)&g_h3lo[idx] = pack_bf2(l0, l1);
                }
            }
        }
    }
}

// ============================================================================
// MLP-2: out = h3 @ Wm2 + bm2   (M=256/blk, N=40, K=256 in two 128-chunks)
// ============================================================================
#define M2_SMEM ((2 * 256 * KP128 + 2 * 40 * KP256) * 2)
__global__ void __launch_bounds__(256, 1)
m2_mma_kernel(const float* __restrict__ Wm2, const float* __restrict__ bm2,
              float* __restrict__ out) {
    extern __shared__ unsigned char smraw[];
    __nv_bfloat16* Ahi = (__nv_bfloat16*)smraw;            // [256][KP128]
    __nv_bfloat16* Alo = Ahi + 256 * KP128;
    __nv_bfloat16* Whi = Alo + 256 * KP128;                // [40][KP256]
    __nv_bfloat16* Wlo = Whi + 40 * KP256;
    int tid = threadIdx.x;
    int node0 = blockIdx.x * 256;

    for (int i = tid; i < 256 * 40; i += 256) {     // Wm2: [256][40] -> Wt[n][k]
        int k = i / 40, n = i % 40;
        __nv_bfloat16 h, l; split2(__ldg(&Wm2[i]), h, l);
        Whi[n * KP256 + k] = h; Wlo[n * KP256 + k] = l;
    }

    int w = tid >> 5, lane = tid & 31, g = lane >> 2, t = lane & 3;
    int m0 = w * 32, n0 = 0;
    float acc[2][5][4];
#pragma unroll
    for (int a = 0; a < 2; a++)
#pragma unroll
        for (int b = 0; b < 5; b++)
#pragma unroll
            for (int c = 0; c < 4; c++) acc[a][b][c] = 0.f;

    for (int kc = 0; kc < 2; kc++) {
        if (kc) __syncthreads();
        for (int i = tid; i < 256 * 64; i += 256) {  // A chunk = copy of h3 hi/lo
            int r = i >> 6, c2 = (i & 63) * 2;
            int gn = node0 + r;
            unsigned vh = 0, vl = 0;
            if (gn < N_NODES) {
                vh = *(const unsigned*)&g_h3hi[(size_t)gn * D_M + kc * 128 + c2];
                vl = *(const unsigned*)&g_h3lo[(size_t)gn * D_M + kc * 128 + c2];
            }
            *(unsigned*)&Ahi[r * KP128 + c2] = vh;
            *(unsigned*)&Alo[r * KP128 + c2] = vl;
        }
        __syncthreads();
#pragma unroll
        for (int ks = 0; ks < 8; ks++)
            mma_step<5>(acc, Ahi, Alo, KP128, Whi, Wlo, KP256,
                        m0, n0, ks * 16, kc * 128 + ks * 16, g, t);
    }

#pragma unroll
    for (int mf = 0; mf < 2; mf++) {
        int r0 = node0 + m0 + mf * 16 + g;
#pragma unroll
        for (int nf = 0; nf < 5; nf++) {
            int col = nf * 8 + t * 2;
            float2 bv = *(const float2*)&bm2[col];
            if (r0 < N_NODES) {
                float2 o = make_float2(acc[mf][nf][0] + bv.x, acc[mf][nf][1] + bv.y);
                *(float2*)&out[(size_t)r0 * D_OUT + col] = o;
            }
            if (r0 + 8 < N_NODES) {
                float2 o = make_float2(acc[mf][nf][2] + bv.x, acc[mf][nf][3] + bv.y);
                *(float2*)&out[(size_t)(r0 + 8) * D_OUT + col] = o;
            }
        }
    }
}

// ---------------- launch -----------------------------------------------------
extern "C" void kernel_launch(void* const* d_in, const int* in_sizes, int n_in,
                              void* d_out, int out_size) {
    const float* feat = (const float*)d_in[0];
    const int*   ei   = (const int*)d_in[1];     // int32 (JAX x64 disabled)
    const float* W1   = (const float*)d_in[2];
    const float* b1   = (const float*)d_in[3];
    const float* W2   = (const float*)d_in[4];
    const float* b2   = (const float*)d_in[5];
    const float* Wm1  = (const float*)d_in[6];
    const float* bm1  = (const float*)d_in[7];
    const float* Wm2  = (const float*)d_in[8];
    const float* bm2  = (const float*)d_in[9];
    float* out = (float*)d_out;

    cudaFuncSetAttribute(l1_mma_kernel, cudaFuncAttributeMaxDynamicSharedMemorySize, L1_SMEM);
    cudaFuncSetAttribute(l2_mma_kernel, cudaFuncAttributeMaxDynamicSharedMemorySize, L2_SMEM);
    cudaFuncSetAttribute(m1_mma_kernel, cudaFuncAttributeMaxDynamicSharedMemorySize, M1_SMEM);
    cudaFuncSetAttribute(m2_mma_kernel, cudaFuncAttributeMaxDynamicSharedMemorySize, M2_SMEM);

    zero_kernel<<<2048, 256>>>();

    scatter1_kernel<<<((unsigned)N_EDGES * 16u + 255) / 256, 256>>>(feat, ei);
    l1_mma_kernel<<<(N_NODES + 127) / 128, 256, L1_SMEM>>>(feat, W1, b1);

    scatter2_kernel<<<((unsigned)N_EDGES * 32u + 255) / 256, 256>>>(ei);
    l2_mma_kernel<<<(N_NODES + 127) / 128, 256, L2_SMEM>>>(W2, b2);

    m1_mma_kernel<<<(N_NODES + 127) / 128, 256, M1_SMEM>>>(Wm1, bm1);
    m2_mma_kernel<<<(N_NODES + 255) / 256, 256, M2_SMEM>>>(Wm2, bm2, out);
}